// round 9
// baseline (speedup 1.0000x reference)
#include <cuda_runtime.h>
#include <cuda_fp16.h>
#include <cstdint>

#define NND 100000
#define NED 3200000
#define HD  64
#define FIN 12
#define EPSBN 1e-5f

// ---------------- static device scratch (no allocations allowed) ----------------
__device__ __align__(16) float  g_bufA[NND * HD];   // fp32 node features (gemm in / agg out)
__device__ __align__(16) __half g_bufH[NND * HD];   // fp16 gemm output (gather table)
__device__ float g_dinv[NND];
__device__ int   g_counts[NND];
__device__ int   g_offsets[NND + 1];
__device__ __align__(16) int g_pos[NED];            // per-edge position within its dst bucket
__device__ __align__(16) int2 g_csr[NED + 8 * NND]; // (src, bitcast dinv[src]); 8-padded segments
__device__ float g_sums[4 * 128];                   // BN partials per layer slot
__device__ int   g_partials[128];                   // scan partials (padded counts)
__device__ int   g_is64;                            // edge_index dtype flag

// ---------------- f32x2 packed-FMA helpers (bit-exact dual fp32) ----------------
__device__ __forceinline__ unsigned long long pack2(float lo, float hi) {
    unsigned long long r;
    asm("mov.b64 %0, {%1, %2};" : "=l"(r) : "f"(lo), "f"(hi));
    return r;
}
__device__ __forceinline__ unsigned long long fma2(unsigned long long a, unsigned long long b,
                                                   unsigned long long c) {
    unsigned long long d;
    asm("fma.rn.f32x2 %0, %1, %2, %3;" : "=l"(d) : "l"(a), "l"(b), "l"(c));
    return d;
}
__device__ __forceinline__ float2 unpack2(unsigned long long v) {
    float2 f;
    asm("mov.b64 {%0, %1}, %2;" : "=f"(f.x), "=f"(f.y) : "l"(v));
    return f;
}

// ---------------- init (+dtype detect folded in) ----------------
__global__ void k_init(const int* ei32) {
    int i = blockIdx.x * blockDim.x + threadIdx.x;
    if (i < NND) g_counts[i] = 0;
    if (i < 4 * 128) g_sums[i] = 0.f;
    if (i == 0) {
        int all0 = 1;
        #pragma unroll
        for (int k = 0; k < 32; k++) {
            if (ei32[2 * k + 1] != 0) all0 = 0;
        }
        g_is64 = all0;
    }
}

// ------- degree histogram: 4 edges/thread, vector loads -------
__global__ void k_hist(const void* ei_) {
    int t4 = blockIdx.x * blockDim.x + threadIdx.x;
    if (t4 >= NED / 4) return;
    int e = t4 * 4;
    int d0, d1, d2, d3;
    if (g_is64) {
        const longlong2* p = (const longlong2*)((const long long*)ei_ + NED + e);
        longlong2 a = p[0], b = p[1];
        d0 = (int)a.x; d1 = (int)a.y; d2 = (int)b.x; d3 = (int)b.y;
    } else {
        int4 a = *(const int4*)((const int*)ei_ + NED + e);
        d0 = a.x; d1 = a.y; d2 = a.z; d3 = a.w;
    }
    int4 p;
    p.x = atomicAdd(&g_counts[d0], 1);
    p.y = atomicAdd(&g_counts[d1], 1);
    p.z = atomicAdd(&g_counts[d2], 1);
    p.w = atomicAdd(&g_counts[d3], 1);
    *(int4*)&g_pos[e] = p;
}

// ---------------- per-1024-chunk totals of PADDED counts ----------------
__global__ void k_scan_a() {
    __shared__ int ws[32];
    int t = threadIdx.x;
    int i = blockIdx.x * 1024 + t;
    int v = (i < NND) ? ((g_counts[i] + 7) & ~7) : 0;
    #pragma unroll
    for (int o = 16; o; o >>= 1) v += __shfl_xor_sync(0xffffffffu, v, o);
    if ((t & 31) == 0) ws[t >> 5] = v;
    __syncthreads();
    if (t < 32) {
        int x = ws[t];
        #pragma unroll
        for (int o = 16; o; o >>= 1) x += __shfl_xor_sync(0xffffffffu, x, o);
        if (t == 0) g_partials[blockIdx.x] = x;
    }
}

// ---- block-local scan of padded counts; fills pad slots with (0, 0.0f) ----
__global__ void k_scan_c() {
    __shared__ int s[2][1024];
    __shared__ int base_sh;
    int t = threadIdx.x;
    int bid = blockIdx.x;
    if (t < 32) {
        int x = 0;
        #pragma unroll
        for (int rep = 0; rep < 4; rep++) {
            int j = rep * 32 + t;
            if (j < bid && j < 98) x += g_partials[j];
        }
        #pragma unroll
        for (int o = 16; o; o >>= 1) x += __shfl_xor_sync(0xffffffffu, x, o);
        if (t == 0) base_sh = x;
    }
    int i = bid * 1024 + t;
    int v = (i < NND) ? g_counts[i] : 0;
    int vp = (v + 7) & ~7;
    s[0][t] = vp;
    __syncthreads();
    int pin = 0;
    #pragma unroll
    for (int off = 1; off < 1024; off <<= 1) {
        int x = s[pin][t];
        if (t >= off) x += s[pin][t - off];
        s[pin ^ 1][t] = x;
        __syncthreads();
        pin ^= 1;
    }
    if (i < NND) {
        int off = s[pin][t] - vp + base_sh;
        g_offsets[i] = off;
        g_dinv[i] = rsqrtf((float)v + 1.0f);
        // fill pad slots (real entries [off, off+v) are written by k_scatter)
        for (int j = v; j < vp; j++) g_csr[off + j] = make_int2(0, 0);
        if (i == NND - 1) g_offsets[NND] = off + vp;
    }
}

// -------- CSR scatter: 4 edges/thread, atomic-free (positions from hist) --------
__global__ void k_scatter(const void* ei_) {
    int t4 = blockIdx.x * blockDim.x + threadIdx.x;
    if (t4 >= NED / 4) return;
    int e = t4 * 4;
    int s0, s1, s2, s3, d0, d1, d2, d3;
    if (g_is64) {
        const longlong2* ps = (const longlong2*)((const long long*)ei_ + e);
        const longlong2* pd = (const longlong2*)((const long long*)ei_ + NED + e);
        longlong2 sa = ps[0], sb = ps[1], da = pd[0], db = pd[1];
        s0 = (int)sa.x; s1 = (int)sa.y; s2 = (int)sb.x; s3 = (int)sb.y;
        d0 = (int)da.x; d1 = (int)da.y; d2 = (int)db.x; d3 = (int)db.y;
    } else {
        int4 sa = *(const int4*)((const int*)ei_ + e);
        int4 da = *(const int4*)((const int*)ei_ + NED + e);
        s0 = sa.x; s1 = sa.y; s2 = sa.z; s3 = sa.w;
        d0 = da.x; d1 = da.y; d2 = da.z; d3 = da.w;
    }
    int4 p = *(const int4*)&g_pos[e];
    g_csr[g_offsets[d0] + p.x] = make_int2(s0, __float_as_int(g_dinv[s0]));
    g_csr[g_offsets[d1] + p.y] = make_int2(s1, __float_as_int(g_dinv[s1]));
    g_csr[g_offsets[d2] + p.z] = make_int2(s2, __float_as_int(g_dinv[s2]));
    g_csr[g_offsets[d3] + p.w] = make_int2(s3, __float_as_int(g_dinv[s3]));
}

// ---------------- input transform: h0 = relu(x @ W_in + b_in) ----------------
__global__ void k_input(const float* __restrict__ x, const float* __restrict__ Win,
                        const float* __restrict__ bin) {
    int gid = blockIdx.x * blockDim.x + threadIdx.x;
    int node = gid >> 4;
    int q = (gid & 15) * 4;
    if (node >= NND) return;
    float4 acc = *(const float4*)&bin[q];
    #pragma unroll
    for (int k = 0; k < FIN; k++) {
        float xv = __ldg(&x[node * FIN + k]);
        float4 w = *(const float4*)&Win[k * HD + q];
        acc.x += xv * w.x; acc.y += xv * w.y; acc.z += xv * w.z; acc.w += xv * w.w;
    }
    acc.x = fmaxf(acc.x, 0.f); acc.y = fmaxf(acc.y, 0.f);
    acc.z = fmaxf(acc.z, 0.f); acc.w = fmaxf(acc.w, 0.f);
    *(float4*)&g_bufA[node * HD + q] = acc;
}

// ------- GEMM: bufH = (relu(BN(bufA)) @ W) as fp16, BN affine computed from g_sums -------
__global__ __launch_bounds__(128, 4) void k_gemm(const float* __restrict__ W,
                                                 const float* __restrict__ gam,
                                                 const float* __restrict__ bet,
                                                 int slot) {
    __shared__ float As[64][128];
    __shared__ float Ws[64 * 64];
    __shared__ float s_scl[64], s_sft[64];
    int t = threadIdx.x;
    if (t < 64) {
        if (slot == 0) {
            s_scl[t] = 1.f; s_sft[t] = 0.f;
        } else {
            float mu  = g_sums[slot * 128 + t] * (1.0f / (float)NND);
            float var = g_sums[slot * 128 + 64 + t] * (1.0f / (float)NND) - mu * mu;
            float scl = gam[t] * rsqrtf(var + EPSBN);
            s_scl[t] = scl;
            s_sft[t] = bet[t] - mu * scl;
        }
    }
    {
        float4* Wsv = (float4*)Ws;
        const float4* Wv = (const float4*)W;
        #pragma unroll
        for (int i = 0; i < 8; i++) Wsv[t + i * 128] = Wv[t + i * 128];
    }
    __syncthreads();

    int base = blockIdx.x * 128;
    int node = base + t;
    if (node < NND) {
        const float4* arow = (const float4*)&g_bufA[node * 64];
        #pragma unroll
        for (int kk = 0; kk < 16; kk++) {
            float4 a = arow[kk];
            int k = kk * 4;
            a.x = fmaxf(a.x * s_scl[k + 0] + s_sft[k + 0], 0.f);
            a.y = fmaxf(a.y * s_scl[k + 1] + s_sft[k + 1], 0.f);
            a.z = fmaxf(a.z * s_scl[k + 2] + s_sft[k + 2], 0.f);
            a.w = fmaxf(a.w * s_scl[k + 3] + s_sft[k + 3], 0.f);
            As[k + 0][t] = a.x; As[k + 1][t] = a.y; As[k + 2][t] = a.z; As[k + 3][t] = a.w;
        }
    } else {
        #pragma unroll
        for (int kk = 0; kk < 16; kk++) {
            int k = kk * 4;
            As[k + 0][t] = 0.f; As[k + 1][t] = 0.f; As[k + 2][t] = 0.f; As[k + 3][t] = 0.f;
        }
    }
    __syncthreads();

    int tx = t & 7, ty = t >> 3;
    int c0 = tx * 8, n0 = ty * 8;
    unsigned long long acc2[4][8];                  // [row-pair ip][col j]
    #pragma unroll
    for (int i = 0; i < 4; i++)
        #pragma unroll
        for (int j = 0; j < 8; j++) acc2[i][j] = 0ull;

    #pragma unroll 8
    for (int k = 0; k < 64; k++) {
        ulonglong2 ap0 = *(const ulonglong2*)&As[k][n0];      // rows (0,1),(2,3)
        ulonglong2 ap1 = *(const ulonglong2*)&As[k][n0 + 4];  // rows (4,5),(6,7)
        float4 w0 = *(const float4*)&Ws[k * 64 + c0];
        float4 w1 = *(const float4*)&Ws[k * 64 + c0 + 4];
        unsigned long long ap[4] = {ap0.x, ap0.y, ap1.x, ap1.y};
        float wv[8] = {w0.x, w0.y, w0.z, w0.w, w1.x, w1.y, w1.z, w1.w};
        #pragma unroll
        for (int j = 0; j < 8; j++) {
            unsigned long long wd = pack2(wv[j], wv[j]);
            #pragma unroll
            for (int ip = 0; ip < 4; ip++)
                acc2[ip][j] = fma2(ap[ip], wd, acc2[ip][j]);
        }
    }

    #pragma unroll
    for (int ip = 0; ip < 4; ip++) {
        float rA[8], rB[8];
        #pragma unroll
        for (int j = 0; j < 8; j++) {
            float2 p = unpack2(acc2[ip][j]);
            rA[j] = p.x; rB[j] = p.y;
        }
        int nA = base + n0 + 2 * ip;
        if (nA < NND) {
            __half2 hs[4];
            hs[0] = __float22half2_rn(make_float2(rA[0], rA[1]));
            hs[1] = __float22half2_rn(make_float2(rA[2], rA[3]));
            hs[2] = __float22half2_rn(make_float2(rA[4], rA[5]));
            hs[3] = __float22half2_rn(make_float2(rA[6], rA[7]));
            *(uint4*)&g_bufH[nA * 64 + c0] = *(const uint4*)hs;
        }
        if (nA + 1 < NND) {
            __half2 hs[4];
            hs[0] = __float22half2_rn(make_float2(rB[0], rB[1]));
            hs[1] = __float22half2_rn(make_float2(rB[2], rB[3]));
            hs[2] = __float22half2_rn(make_float2(rB[4], rB[5]));
            hs[3] = __float22half2_rn(make_float2(rB[6], rB[7]));
            *(uint4*)&g_bufH[(nA + 1) * 64 + c0] = *(const uint4*)hs;
        }
    }
}

// ---- aggregation (+fused BN stats), SHFL-free: CSR read via uniform L1-broadcast loads ----
__global__ __launch_bounds__(256) void k_agg(const float* __restrict__ bias, int slot) {
    __shared__ float s_acc[128];            // 64 col sums + 64 col sumsq
    int t = threadIdx.x;
    if (t < 128) s_acc[t] = 0.f;
    __syncthreads();

    int wid = (blockIdx.x * blockDim.x + t) >> 5;
    int lane = t & 31;
    const __half* __restrict__ T = g_bufH;

    int beg = g_offsets[wid];               // multiple of 8
    int end = g_offsets[wid + 1];           // multiple of 8; pads carry (0, 0.0f)
    float ax = 0.f, ay = 0.f;

    for (int e0 = beg; e0 < end; e0 += 8) {
        const int4* cp = (const int4*)&g_csr[e0];   // uniform across warp -> L1 broadcast
        int4 c0 = __ldg(cp + 0);
        int4 c1 = __ldg(cp + 1);
        int4 c2 = __ldg(cp + 2);
        int4 c3 = __ldg(cp + 3);
        __half2 hv[8];
        hv[0] = *(const __half2*)&T[c0.x * 64 + 2 * lane];
        hv[1] = *(const __half2*)&T[c0.z * 64 + 2 * lane];
        hv[2] = *(const __half2*)&T[c1.x * 64 + 2 * lane];
        hv[3] = *(const __half2*)&T[c1.z * 64 + 2 * lane];
        hv[4] = *(const __half2*)&T[c2.x * 64 + 2 * lane];
        hv[5] = *(const __half2*)&T[c2.z * 64 + 2 * lane];
        hv[6] = *(const __half2*)&T[c3.x * 64 + 2 * lane];
        hv[7] = *(const __half2*)&T[c3.z * 64 + 2 * lane];
        float ws[8] = {__int_as_float(c0.y), __int_as_float(c0.w),
                       __int_as_float(c1.y), __int_as_float(c1.w),
                       __int_as_float(c2.y), __int_as_float(c2.w),
                       __int_as_float(c3.y), __int_as_float(c3.w)};
        #pragma unroll
        for (int u = 0; u < 8; u++) {
            float2 v = __half22float2(hv[u]);
            ax = fmaf(ws[u], v.x, ax);
            ay = fmaf(ws[u], v.y, ay);
        }
    }

    float dn = g_dinv[wid];
    float sn = dn * dn;
    float2 self = __half22float2(*(const __half2*)&T[wid * 64 + 2 * lane]);
    float2 o;
    o.x = dn * ax + sn * self.x + bias[2 * lane + 0];
    o.y = dn * ay + sn * self.y + bias[2 * lane + 1];
    *(float2*)&g_bufA[wid * 64 + 2 * lane] = o;

    // fused BN stats into this layer's slot
    atomicAdd(&s_acc[2 * lane + 0], o.x);
    atomicAdd(&s_acc[2 * lane + 1], o.y);
    atomicAdd(&s_acc[64 + 2 * lane + 0], o.x * o.x);
    atomicAdd(&s_acc[64 + 2 * lane + 1], o.y * o.y);
    __syncthreads();
    if (t < 128) atomicAdd(&g_sums[slot * 128 + t], s_acc[t]);
}

// -------- classifier head: out = relu(BN(bufA) @ Wc1 + bc1) @ Wc2 + bc2 --------
__global__ void k_cls(const float* __restrict__ Wc1, const float* __restrict__ bc1,
                      const float* __restrict__ Wc2, const float* __restrict__ bc2,
                      const float* __restrict__ gam, const float* __restrict__ bet,
                      float* __restrict__ out) {
    __shared__ float w1[64 * 32];
    __shared__ float sscl[64], ssft[64], sb1[32], w2s[64], b2s[2];
    int t = threadIdx.x;
    for (int i = t; i < 2048; i += blockDim.x) w1[i] = Wc1[i];
    if (t < 64) {
        float mu  = g_sums[3 * 128 + t] * (1.0f / (float)NND);
        float var = g_sums[3 * 128 + 64 + t] * (1.0f / (float)NND) - mu * mu;
        float scl = gam[t] * rsqrtf(var + EPSBN);
        sscl[t] = scl;
        ssft[t] = bet[t] - mu * scl;
        w2s[t] = Wc2[t];
    }
    if (t < 32) sb1[t] = bc1[t];
    if (t < 2)  b2s[t] = bc2[t];
    __syncthreads();

    int wid = (blockIdx.x * blockDim.x + t) >> 5;
    if (wid >= NND) return;
    int lane = t & 31;

    float2 v = *(const float2*)&g_bufA[wid * 64 + 2 * lane];
    v.x = v.x * sscl[2 * lane + 0] + ssft[2 * lane + 0];
    v.y = v.y * sscl[2 * lane + 1] + ssft[2 * lane + 1];

    float u = sb1[lane];
    #pragma unroll
    for (int p = 0; p < 32; p++) {
        float a = __shfl_sync(0xffffffffu, v.x, p);
        float b = __shfl_sync(0xffffffffu, v.y, p);
        u = fmaf(a, w1[(2 * p + 0) * 32 + lane], u);
        u = fmaf(b, w1[(2 * p + 1) * 32 + lane], u);
    }
    u = fmaxf(u, 0.f);

    float o0 = fmaf(u, w2s[lane * 2 + 0], b2s[0] * (1.0f / 32.0f));
    float o1 = fmaf(u, w2s[lane * 2 + 1], b2s[1] * (1.0f / 32.0f));
    #pragma unroll
    for (int off = 16; off; off >>= 1) {
        o0 += __shfl_xor_sync(0xffffffffu, o0, off);
        o1 += __shfl_xor_sync(0xffffffffu, o1, off);
    }
    if (lane == 0) {
        out[wid * 2 + 0] = o0;
        out[wid * 2 + 1] = o1;
    }
}

// ---------------- host launch sequence (graph-capturable, two-stream fork-join) ----------------
extern "C" void kernel_launch(void* const* d_in, const int* in_sizes, int n_in,
                              void* d_out, int out_size) {
    const float* x     = (const float*)d_in[0];
    const void*  ei    = d_in[1];
    const float* Win   = (const float*)d_in[2];
    const float* bin   = (const float*)d_in[3];
    const float* Wg    = (const float*)d_in[4];   // [3,64,64]
    const float* bg    = (const float*)d_in[5];   // [3,64]
    const float* gamma = (const float*)d_in[6];   // [3,64]
    const float* beta  = (const float*)d_in[7];   // [3,64]
    const float* Wc1   = (const float*)d_in[8];
    const float* bc1   = (const float*)d_in[9];
    const float* Wc2   = (const float*)d_in[10];
    const float* bc2   = (const float*)d_in[11];
    float* out = (float*)d_out;

    // Created once on the first (uncaptured, correctness) call; reused during capture.
    static cudaStream_t s2 = nullptr;
    static cudaEvent_t evFork = nullptr, evJoin = nullptr;
    if (s2 == nullptr) {
        cudaStreamCreateWithFlags(&s2, cudaStreamNonBlocking);
        cudaEventCreateWithFlags(&evFork, cudaEventDisableTiming);
        cudaEventCreateWithFlags(&evJoin, cudaEventDisableTiming);
    }

    // Fork: side stream does the dense path (input + gemm0) while the main
    // stream builds the CSR (hist/scan/scatter) — disjoint buffers, disjoint pipes.
    cudaEventRecord(evFork, 0);
    cudaStreamWaitEvent(s2, evFork, 0);
    k_input<<<(NND * 16 + 255) / 256, 256, 0, s2>>>(x, Win, bin);
    k_gemm<<<(NND + 127) / 128, 128, 0, s2>>>(Wg, gamma, beta, 0);
    cudaEventRecord(evJoin, s2);

    k_init<<<(NND + 255) / 256, 256>>>((const int*)ei);
    k_hist<<<(NED / 4 + 255) / 256, 256>>>(ei);
    k_scan_a<<<98, 1024>>>();
    k_scan_c<<<98, 1024>>>();
    k_scatter<<<(NED / 4 + 255) / 256, 256>>>(ei);

    cudaStreamWaitEvent(0, evJoin, 0);           // join before first aggregation

    k_agg<<<NND / 8, 256>>>(bg, 1);
    k_gemm<<<(NND + 127) / 128, 128>>>(Wg + 4096, gamma, beta, 1);
    k_agg<<<NND / 8, 256>>>(bg + 64, 2);
    k_gemm<<<(NND + 127) / 128, 128>>>(Wg + 8192, gamma + 64, beta + 64, 2);
    k_agg<<<NND / 8, 256>>>(bg + 128, 3);

    k_cls<<<NND / 8, 256>>>(Wc1, bc1, Wc2, bc2, gamma + 128, beta + 128, out);
}

// round 10
// speedup vs baseline: 1.0612x; 1.0612x over previous
#include <cuda_runtime.h>
#include <cuda_fp16.h>
#include <cstdint>

#define NND 100000
#define NED 3200000
#define HD  64
#define FIN 12
#define EPSBN 1e-5f

// ---------------- static device scratch (no allocations allowed) ----------------
__device__ __align__(256) float  g_bufA[NND * HD];  // fp32 node features (gemm in / agg out)
__device__ __align__(256) __half g_bufH[NND * HD];  // fp16 gemm output (gather table) — 128B-line aligned
__device__ float g_dinv[NND];
__device__ int   g_counts[NND];
__device__ int   g_offsets[NND + 1];
__device__ __align__(16) int g_pos[NED];            // per-edge position within its dst bucket
__device__ __align__(256) int2 g_csr[NED];          // (src, bitcast dinv[src])
__device__ float g_sums[4 * 128];                   // BN partials per layer slot
__device__ int   g_partials[128];                   // scan partials
__device__ int   g_is64;                            // edge_index dtype flag

// ---------------- f32x2 packed-FMA helpers (bit-exact dual fp32) ----------------
__device__ __forceinline__ unsigned long long pack2(float lo, float hi) {
    unsigned long long r;
    asm("mov.b64 %0, {%1, %2};" : "=l"(r) : "f"(lo), "f"(hi));
    return r;
}
__device__ __forceinline__ unsigned long long fma2(unsigned long long a, unsigned long long b,
                                                   unsigned long long c) {
    unsigned long long d;
    asm("fma.rn.f32x2 %0, %1, %2, %3;" : "=l"(d) : "l"(a), "l"(b), "l"(c));
    return d;
}
__device__ __forceinline__ float2 unpack2(unsigned long long v) {
    float2 f;
    asm("mov.b64 {%0, %1}, %2;" : "=f"(f.x), "=f"(f.y) : "l"(v));
    return f;
}

// ---------------- init (+dtype detect folded in) ----------------
__global__ void k_init(const int* ei32) {
    int i = blockIdx.x * blockDim.x + threadIdx.x;
    if (i < NND) g_counts[i] = 0;
    if (i < 4 * 128) g_sums[i] = 0.f;
    if (i == 0) {
        g_offsets[NND] = NED;
        int all0 = 1;
        #pragma unroll
        for (int k = 0; k < 32; k++) {
            if (ei32[2 * k + 1] != 0) all0 = 0;
        }
        g_is64 = all0;
    }
}

// ------- degree histogram: 4 edges/thread, vector loads -------
__global__ void k_hist(const void* ei_) {
    int t4 = blockIdx.x * blockDim.x + threadIdx.x;
    if (t4 >= NED / 4) return;
    int e = t4 * 4;
    int d0, d1, d2, d3;
    if (g_is64) {
        const longlong2* p = (const longlong2*)((const long long*)ei_ + NED + e);
        longlong2 a = p[0], b = p[1];
        d0 = (int)a.x; d1 = (int)a.y; d2 = (int)b.x; d3 = (int)b.y;
    } else {
        int4 a = *(const int4*)((const int*)ei_ + NED + e);
        d0 = a.x; d1 = a.y; d2 = a.z; d3 = a.w;
    }
    int4 p;
    p.x = atomicAdd(&g_counts[d0], 1);
    p.y = atomicAdd(&g_counts[d1], 1);
    p.z = atomicAdd(&g_counts[d2], 1);
    p.w = atomicAdd(&g_counts[d3], 1);
    *(int4*)&g_pos[e] = p;
}

// ---------------- per-1024-chunk totals ----------------
__global__ void k_scan_a() {
    __shared__ int ws[32];
    int t = threadIdx.x;
    int i = blockIdx.x * 1024 + t;
    int v = (i < NND) ? g_counts[i] : 0;
    #pragma unroll
    for (int o = 16; o; o >>= 1) v += __shfl_xor_sync(0xffffffffu, v, o);
    if ((t & 31) == 0) ws[t >> 5] = v;
    __syncthreads();
    if (t < 32) {
        int x = ws[t];
        #pragma unroll
        for (int o = 16; o; o >>= 1) x += __shfl_xor_sync(0xffffffffu, x, o);
        if (t == 0) g_partials[blockIdx.x] = x;
    }
}

// ---------------- block-local scan; block base = sum of preceding partials ----------------
__global__ void k_scan_c() {
    __shared__ int s[2][1024];
    __shared__ int base_sh;
    int t = threadIdx.x;
    int bid = blockIdx.x;
    if (t < 32) {
        int x = 0;
        #pragma unroll
        for (int rep = 0; rep < 4; rep++) {
            int j = rep * 32 + t;
            if (j < bid && j < 98) x += g_partials[j];
        }
        #pragma unroll
        for (int o = 16; o; o >>= 1) x += __shfl_xor_sync(0xffffffffu, x, o);
        if (t == 0) base_sh = x;
    }
    int i = bid * 1024 + t;
    int v = (i < NND) ? g_counts[i] : 0;
    s[0][t] = v;
    __syncthreads();
    int pin = 0;
    #pragma unroll
    for (int off = 1; off < 1024; off <<= 1) {
        int x = s[pin][t];
        if (t >= off) x += s[pin][t - off];
        s[pin ^ 1][t] = x;
        __syncthreads();
        pin ^= 1;
    }
    if (i < NND) {
        g_offsets[i] = s[pin][t] - v + base_sh;
        g_dinv[i] = rsqrtf((float)v + 1.0f);
    }
}

// -------- CSR scatter: 4 edges/thread, atomic-free (positions from hist) --------
__global__ void k_scatter(const void* ei_) {
    int t4 = blockIdx.x * blockDim.x + threadIdx.x;
    if (t4 >= NED / 4) return;
    int e = t4 * 4;
    int s0, s1, s2, s3, d0, d1, d2, d3;
    if (g_is64) {
        const longlong2* ps = (const longlong2*)((const long long*)ei_ + e);
        const longlong2* pd = (const longlong2*)((const long long*)ei_ + NED + e);
        longlong2 sa = ps[0], sb = ps[1], da = pd[0], db = pd[1];
        s0 = (int)sa.x; s1 = (int)sa.y; s2 = (int)sb.x; s3 = (int)sb.y;
        d0 = (int)da.x; d1 = (int)da.y; d2 = (int)db.x; d3 = (int)db.y;
    } else {
        int4 sa = *(const int4*)((const int*)ei_ + e);
        int4 da = *(const int4*)((const int*)ei_ + NED + e);
        s0 = sa.x; s1 = sa.y; s2 = sa.z; s3 = sa.w;
        d0 = da.x; d1 = da.y; d2 = da.z; d3 = da.w;
    }
    int4 p = *(const int4*)&g_pos[e];
    g_csr[g_offsets[d0] + p.x] = make_int2(s0, __float_as_int(g_dinv[s0]));
    g_csr[g_offsets[d1] + p.y] = make_int2(s1, __float_as_int(g_dinv[s1]));
    g_csr[g_offsets[d2] + p.z] = make_int2(s2, __float_as_int(g_dinv[s2]));
    g_csr[g_offsets[d3] + p.w] = make_int2(s3, __float_as_int(g_dinv[s3]));
}

// ---------------- input transform: h0 = relu(x @ W_in + b_in) ----------------
__global__ void k_input(const float* __restrict__ x, const float* __restrict__ Win,
                        const float* __restrict__ bin) {
    int gid = blockIdx.x * blockDim.x + threadIdx.x;
    int node = gid >> 4;
    int q = (gid & 15) * 4;
    if (node >= NND) return;
    float4 acc = *(const float4*)&bin[q];
    #pragma unroll
    for (int k = 0; k < FIN; k++) {
        float xv = __ldg(&x[node * FIN + k]);
        float4 w = *(const float4*)&Win[k * HD + q];
        acc.x += xv * w.x; acc.y += xv * w.y; acc.z += xv * w.z; acc.w += xv * w.w;
    }
    acc.x = fmaxf(acc.x, 0.f); acc.y = fmaxf(acc.y, 0.f);
    acc.z = fmaxf(acc.z, 0.f); acc.w = fmaxf(acc.w, 0.f);
    *(float4*)&g_bufA[node * HD + q] = acc;
}

// ------- GEMM: bufH = (relu(BN(bufA)) @ W) as fp16, BN affine computed from g_sums -------
__global__ __launch_bounds__(128, 4) void k_gemm(const float* __restrict__ W,
                                                 const float* __restrict__ gam,
                                                 const float* __restrict__ bet,
                                                 int slot) {
    __shared__ float As[64][128];
    __shared__ float Ws[64 * 64];
    __shared__ float s_scl[64], s_sft[64];
    int t = threadIdx.x;
    if (t < 64) {
        if (slot == 0) {
            s_scl[t] = 1.f; s_sft[t] = 0.f;
        } else {
            float mu  = g_sums[slot * 128 + t] * (1.0f / (float)NND);
            float var = g_sums[slot * 128 + 64 + t] * (1.0f / (float)NND) - mu * mu;
            float scl = gam[t] * rsqrtf(var + EPSBN);
            s_scl[t] = scl;
            s_sft[t] = bet[t] - mu * scl;
        }
    }
    {
        float4* Wsv = (float4*)Ws;
        const float4* Wv = (const float4*)W;
        #pragma unroll
        for (int i = 0; i < 8; i++) Wsv[t + i * 128] = Wv[t + i * 128];
    }
    __syncthreads();

    int base = blockIdx.x * 128;
    int node = base + t;
    if (node < NND) {
        const float4* arow = (const float4*)&g_bufA[node * 64];
        #pragma unroll
        for (int kk = 0; kk < 16; kk++) {
            float4 a = arow[kk];
            int k = kk * 4;
            a.x = fmaxf(a.x * s_scl[k + 0] + s_sft[k + 0], 0.f);
            a.y = fmaxf(a.y * s_scl[k + 1] + s_sft[k + 1], 0.f);
            a.z = fmaxf(a.z * s_scl[k + 2] + s_sft[k + 2], 0.f);
            a.w = fmaxf(a.w * s_scl[k + 3] + s_sft[k + 3], 0.f);
            As[k + 0][t] = a.x; As[k + 1][t] = a.y; As[k + 2][t] = a.z; As[k + 3][t] = a.w;
        }
    } else {
        #pragma unroll
        for (int kk = 0; kk < 16; kk++) {
            int k = kk * 4;
            As[k + 0][t] = 0.f; As[k + 1][t] = 0.f; As[k + 2][t] = 0.f; As[k + 3][t] = 0.f;
        }
    }
    __syncthreads();

    int tx = t & 7, ty = t >> 3;
    int c0 = tx * 8, n0 = ty * 8;
    unsigned long long acc2[4][8];                  // [row-pair ip][col j]
    #pragma unroll
    for (int i = 0; i < 4; i++)
        #pragma unroll
        for (int j = 0; j < 8; j++) acc2[i][j] = 0ull;

    #pragma unroll 8
    for (int k = 0; k < 64; k++) {
        ulonglong2 ap0 = *(const ulonglong2*)&As[k][n0];      // rows (0,1),(2,3)
        ulonglong2 ap1 = *(const ulonglong2*)&As[k][n0 + 4];  // rows (4,5),(6,7)
        float4 w0 = *(const float4*)&Ws[k * 64 + c0];
        float4 w1 = *(const float4*)&Ws[k * 64 + c0 + 4];
        unsigned long long ap[4] = {ap0.x, ap0.y, ap1.x, ap1.y};
        float wv[8] = {w0.x, w0.y, w0.z, w0.w, w1.x, w1.y, w1.z, w1.w};
        #pragma unroll
        for (int j = 0; j < 8; j++) {
            unsigned long long wd = pack2(wv[j], wv[j]);
            #pragma unroll
            for (int ip = 0; ip < 4; ip++)
                acc2[ip][j] = fma2(ap[ip], wd, acc2[ip][j]);
        }
    }

    #pragma unroll
    for (int ip = 0; ip < 4; ip++) {
        float rA[8], rB[8];
        #pragma unroll
        for (int j = 0; j < 8; j++) {
            float2 p = unpack2(acc2[ip][j]);
            rA[j] = p.x; rB[j] = p.y;
        }
        int nA = base + n0 + 2 * ip;
        if (nA < NND) {
            __half2 hs[4];
            hs[0] = __float22half2_rn(make_float2(rA[0], rA[1]));
            hs[1] = __float22half2_rn(make_float2(rA[2], rA[3]));
            hs[2] = __float22half2_rn(make_float2(rA[4], rA[5]));
            hs[3] = __float22half2_rn(make_float2(rA[6], rA[7]));
            *(uint4*)&g_bufH[nA * 64 + c0] = *(const uint4*)hs;
        }
        if (nA + 1 < NND) {
            __half2 hs[4];
            hs[0] = __float22half2_rn(make_float2(rB[0], rB[1]));
            hs[1] = __float22half2_rn(make_float2(rB[2], rB[3]));
            hs[2] = __float22half2_rn(make_float2(rB[4], rB[5]));
            hs[3] = __float22half2_rn(make_float2(rB[6], rB[7]));
            *(uint4*)&g_bufH[(nA + 1) * 64 + c0] = *(const uint4*)hs;
        }
    }
}

// ---- aggregation (+fused BN stats): bufA[d] = dinv[d]*sum w_e*h[src] + dinv^2*h[d] + b ----
// SHFL-batched gather loop (best known); BN stats via conflict-padded STS tree (no smem atomics).
__global__ __launch_bounds__(256) void k_agg(const float* __restrict__ bias, int slot) {
    __shared__ float s_red[128 * 9];        // col c at s_red[c*9 + warp]; degree-2 max conflicts
    int t = threadIdx.x;
    int w = t >> 5;
    int lane = t & 31;
    int wid = (blockIdx.x * blockDim.x + t) >> 5;
    const __half* __restrict__ T = g_bufH;

    int beg = g_offsets[wid];
    int end = g_offsets[wid + 1];
    float ax = 0.f, ay = 0.f;

    for (int e0 = beg; e0 < end; e0 += 32) {
        int e = e0 + lane;
        int2 sw = (e < end) ? g_csr[e] : make_int2(0, 0);
        int cnt = end - e0;                  // >0; may exceed 32
        #pragma unroll
        for (int jb = 0; jb < 4; jb++) {
            if (jb * 8 >= cnt) break;        // only skips when cnt < 32
            int ss[8]; float ww[8]; __half2 hv[8];
            #pragma unroll
            for (int u = 0; u < 8; u++) {
                ss[u] = __shfl_sync(0xffffffffu, sw.x, jb * 8 + u);
                ww[u] = __int_as_float(__shfl_sync(0xffffffffu, sw.y, jb * 8 + u));
            }
            #pragma unroll
            for (int u = 0; u < 8; u++)
                hv[u] = *(const __half2*)&T[ss[u] * 64 + 2 * lane];
            #pragma unroll
            for (int u = 0; u < 8; u++) {
                float2 v = __half22float2(hv[u]);
                ax = fmaf(ww[u], v.x, ax);
                ay = fmaf(ww[u], v.y, ay);
            }
        }
    }

    float dn = g_dinv[wid];
    float sn = dn * dn;
    float2 self = __half22float2(*(const __half2*)&T[wid * 64 + 2 * lane]);
    float2 o;
    o.x = dn * ax + sn * self.x + bias[2 * lane + 0];
    o.y = dn * ay + sn * self.y + bias[2 * lane + 1];
    *(float2*)&g_bufA[wid * 64 + 2 * lane] = o;

    // fused BN stats: per-warp STS into padded layout, tree-read, 128 global atomics/block
    s_red[(2 * lane + 0) * 9 + w] = o.x;
    s_red[(2 * lane + 1) * 9 + w] = o.y;
    s_red[(64 + 2 * lane + 0) * 9 + w] = o.x * o.x;
    s_red[(64 + 2 * lane + 1) * 9 + w] = o.y * o.y;
    __syncthreads();
    if (t < 128) {
        float s = 0.f;
        #pragma unroll
        for (int u = 0; u < 8; u++) s += s_red[t * 9 + u];
        atomicAdd(&g_sums[slot * 128 + t], s);
    }
}

// -------- classifier head: out = relu(BN(bufA) @ Wc1 + bc1) @ Wc2 + bc2 --------
__global__ void k_cls(const float* __restrict__ Wc1, const float* __restrict__ bc1,
                      const float* __restrict__ Wc2, const float* __restrict__ bc2,
                      const float* __restrict__ gam, const float* __restrict__ bet,
                      float* __restrict__ out) {
    __shared__ float w1[64 * 32];
    __shared__ float sscl[64], ssft[64], sb1[32], w2s[64], b2s[2];
    int t = threadIdx.x;
    for (int i = t; i < 2048; i += blockDim.x) w1[i] = Wc1[i];
    if (t < 64) {
        float mu  = g_sums[3 * 128 + t] * (1.0f / (float)NND);
        float var = g_sums[3 * 128 + 64 + t] * (1.0f / (float)NND) - mu * mu;
        float scl = gam[t] * rsqrtf(var + EPSBN);
        sscl[t] = scl;
        ssft[t] = bet[t] - mu * scl;
        w2s[t] = Wc2[t];
    }
    if (t < 32) sb1[t] = bc1[t];
    if (t < 2)  b2s[t] = bc2[t];
    __syncthreads();

    int wid = (blockIdx.x * blockDim.x + t) >> 5;
    if (wid >= NND) return;
    int lane = t & 31;

    float2 v = *(const float2*)&g_bufA[wid * 64 + 2 * lane];
    v.x = v.x * sscl[2 * lane + 0] + ssft[2 * lane + 0];
    v.y = v.y * sscl[2 * lane + 1] + ssft[2 * lane + 1];

    float u = sb1[lane];
    #pragma unroll
    for (int p = 0; p < 32; p++) {
        float a = __shfl_sync(0xffffffffu, v.x, p);
        float b = __shfl_sync(0xffffffffu, v.y, p);
        u = fmaf(a, w1[(2 * p + 0) * 32 + lane], u);
        u = fmaf(b, w1[(2 * p + 1) * 32 + lane], u);
    }
    u = fmaxf(u, 0.f);

    float o0 = fmaf(u, w2s[lane * 2 + 0], b2s[0] * (1.0f / 32.0f));
    float o1 = fmaf(u, w2s[lane * 2 + 1], b2s[1] * (1.0f / 32.0f));
    #pragma unroll
    for (int off = 16; off; off >>= 1) {
        o0 += __shfl_xor_sync(0xffffffffu, o0, off);
        o1 += __shfl_xor_sync(0xffffffffu, o1, off);
    }
    if (lane == 0) {
        out[wid * 2 + 0] = o0;
        out[wid * 2 + 1] = o1;
    }
}

// ---------------- host launch sequence (graph-capturable, two-stream fork-join) ----------------
extern "C" void kernel_launch(void* const* d_in, const int* in_sizes, int n_in,
                              void* d_out, int out_size) {
    const float* x     = (const float*)d_in[0];
    const void*  ei    = d_in[1];
    const float* Win   = (const float*)d_in[2];
    const float* bin   = (const float*)d_in[3];
    const float* Wg    = (const float*)d_in[4];   // [3,64,64]
    const float* bg    = (const float*)d_in[5];   // [3,64]
    const float* gamma = (const float*)d_in[6];   // [3,64]
    const float* beta  = (const float*)d_in[7];   // [3,64]
    const float* Wc1   = (const float*)d_in[8];
    const float* bc1   = (const float*)d_in[9];
    const float* Wc2   = (const float*)d_in[10];
    const float* bc2   = (const float*)d_in[11];
    float* out = (float*)d_out;

    // Created once on the first (uncaptured, correctness) call; reused during capture.
    static cudaStream_t s2 = nullptr;
    static cudaEvent_t evFork = nullptr, evJoin = nullptr;
    if (s2 == nullptr) {
        cudaStreamCreateWithFlags(&s2, cudaStreamNonBlocking);
        cudaEventCreateWithFlags(&evFork, cudaEventDisableTiming);
        cudaEventCreateWithFlags(&evJoin, cudaEventDisableTiming);
    }

    // Fork: side stream does the dense path (input + gemm0) while the main
    // stream builds the CSR (hist/scan/scatter) — disjoint buffers, disjoint pipes.
    cudaEventRecord(evFork, 0);
    cudaStreamWaitEvent(s2, evFork, 0);
    k_input<<<(NND * 16 + 255) / 256, 256, 0, s2>>>(x, Win, bin);
    k_gemm<<<(NND + 127) / 128, 128, 0, s2>>>(Wg, gamma, beta, 0);
    cudaEventRecord(evJoin, s2);

    k_init<<<(NND + 255) / 256, 256>>>((const int*)ei);
    k_hist<<<(NED / 4 + 255) / 256, 256>>>(ei);
    k_scan_a<<<98, 1024>>>();
    k_scan_c<<<98, 1024>>>();
    k_scatter<<<(NED / 4 + 255) / 256, 256>>>(ei);

    cudaStreamWaitEvent(0, evJoin, 0);           // join before first aggregation

    k_agg<<<NND / 8, 256>>>(bg, 1);
    k_gemm<<<(NND + 127) / 128, 128>>>(Wg + 4096, gamma, beta, 1);
    k_agg<<<NND / 8, 256>>>(bg + 64, 2);
    k_gemm<<<(NND + 127) / 128, 128>>>(Wg + 8192, gamma + 64, beta + 64, 2);
    k_agg<<<NND / 8, 256>>>(bg + 128, 3);

    k_cls<<<NND / 8, 256>>>(Wc1, bc1, Wc2, bc2, gamma + 128, beta + 128, out);
}